// round 3
// baseline (speedup 1.0000x reference)
#include <cuda_runtime.h>
#include <cuda_bf16.h>

// Problem constants (fixed for this bench):
//   data:       [200000, 5]  float32
//   clusts:     [2000, 100]  int32   (200000 entries total)
//   edge_index: [2, 32000]   int32
//   W:          [5, 16]      float32
//   out:        [32000*200, 16] float32
//
// Decomposition: out[row, f] = relu( d0*W[0,f] + d1*W[1,f] + d2*W[2,f]
//                                    + d4*W[4,f] + eid*W[3,f] )
// The first 4 terms depend only on (cluster, pos) -> precompute into g_base
// (12.8 MB, L2-resident on re-read). Each base row is reused ~32x.

#define VPC   100          // CLUST_SIZE
#define NF    16           // N_FEAT
#define MAX_BASE_ENTRIES (2000 * 100)   // N_CLUST * CLUST_SIZE

// 12.8 MB scratch: per-(cluster,pos) partial feature rows, stored as float4[4].
__device__ float4 g_base[MAX_BASE_ENTRIES * (NF / 4)];

// ---------------------------------------------------------------------------
// Kernel 1: precompute base[c*V+p][0..15] = d0*W0 + d1*W1 + d2*W2 + d4*W4
// One thread per (cluster, pos) entry. W is tiny (80 floats) -> L1 broadcast.
// ---------------------------------------------------------------------------
__global__ void precompute_base_kernel(const float* __restrict__ data,
                                       const int*   __restrict__ clusts,
                                       const float* __restrict__ W,
                                       int total)
{
    int idx = blockIdx.x * blockDim.x + threadIdx.x;
    if (idx >= total) return;

    int v = clusts[idx];
    const float* dp = data + (long long)v * 5;
    float d0 = dp[0];
    float d1 = dp[1];
    float d2 = dp[2];
    float d4 = dp[4];   // column 3 is replaced by edge id later

    float4* out = g_base + idx * (NF / 4);
#pragma unroll
    for (int q = 0; q < NF / 4; q++) {
        float4 r;
        float* rp = reinterpret_cast<float*>(&r);
#pragma unroll
        for (int j = 0; j < 4; j++) {
            int f = q * 4 + j;
            rp[j] = d0 * __ldg(&W[0 * NF + f])
                  + d1 * __ldg(&W[1 * NF + f])
                  + d2 * __ldg(&W[2 * NF + f])
                  + d4 * __ldg(&W[4 * NF + f]);
        }
        out[q] = r;
    }
}

// ---------------------------------------------------------------------------
// Kernel 2: EPB edges per block, 256 threads. Per edge: 2V rows * NF floats
// = 800 float4. f4 = tid & 3 is loop-invariant (stride 256 divisible by 4),
// so the per-thread eid*W3 offset vector is computed once per edge.
// Reads of g_base (12.8 MB) are L2-resident; stores are fully coalesced.
// ---------------------------------------------------------------------------
#define EPB 4   // edges per block

__global__ __launch_bounds__(256)
void edge_feature_kernel(const int*   __restrict__ edge_index,
                         const float* __restrict__ W,
                         float4*      __restrict__ out,
                         int E)
{
    const int t  = threadIdx.x;
    const int f4 = t & 3;

    // Per-thread W[3] slice (loop-invariant across edges).
    const float* W3 = W + 3 * NF + f4 * 4;
    const float w3x = __ldg(&W3[0]);
    const float w3y = __ldg(&W3[1]);
    const float w3z = __ldg(&W3[2]);
    const float w3w = __ldg(&W3[3]);

    const int F4_PER_EDGE = 2 * VPC * (NF / 4);  // 800

#pragma unroll
    for (int ee = 0; ee < EPB; ee++) {
        const int e = blockIdx.x * EPB + ee;
        if (e >= E) return;

        const int c0 = __ldg(&edge_index[e]);        // src cluster
        const int c1 = __ldg(&edge_index[E + e]);    // dst cluster
        const float eidf = (float)e;

        float4 off;
        off.x = eidf * w3x;
        off.y = eidf * w3y;
        off.z = eidf * w3z;
        off.w = eidf * w3w;

        float4* dst = out + (long long)e * F4_PER_EDGE;

#pragma unroll
        for (int k = 0; k < 4; k++) {
            int i = t + k * 256;
            if (i < F4_PER_EDGE) {
                int row = i >> 2;                       // 0..199
                int c   = (row < VPC) ? c0 : c1;
                int p   = (row < VPC) ? row : row - VPC;
                float4 b = g_base[(c * VPC + p) * (NF / 4) + f4];
                float4 r;
                r.x = fmaxf(b.x + off.x, 0.0f);
                r.y = fmaxf(b.y + off.y, 0.0f);
                r.z = fmaxf(b.z + off.z, 0.0f);
                r.w = fmaxf(b.w + off.w, 0.0f);
                dst[i] = r;
            }
        }
    }
}

// ---------------------------------------------------------------------------
// kernel_launch: graph-capturable, allocation-free.
// Input order (metadata): data, clusts, edge_index, W.
// ---------------------------------------------------------------------------
extern "C" void kernel_launch(void* const* d_in, const int* in_sizes, int n_in,
                              void* d_out, int out_size)
{
    const float* data       = (const float*)d_in[0];
    const int*   clusts     = (const int*)  d_in[1];
    const int*   edge_index = (const int*)  d_in[2];
    const float* W          = (const float*)d_in[3];

    const int total_entries = in_sizes[1];      // N_CLUST * CLUST_SIZE = 200000
    const int E             = in_sizes[2] / 2;  // 32000

    // Kernel 1: fill g_base
    {
        int threads = 256;
        int blocks = (total_entries + threads - 1) / threads;
        precompute_base_kernel<<<blocks, threads>>>(data, clusts, W, total_entries);
    }

    // Kernel 2: EPB edges per block
    {
        int blocks = (E + EPB - 1) / EPB;
        edge_feature_kernel<<<blocks, 256>>>(edge_index, W, (float4*)d_out, E);
    }
}

// round 4
// speedup vs baseline: 1.0765x; 1.0765x over previous
#include <cuda_runtime.h>
#include <cuda_bf16.h>

// Problem constants (fixed for this bench):
//   data:       [200000, 5]  float32
//   clusts:     [2000, 100]  int32   (200000 entries total)
//   edge_index: [2, 32000]   int32
//   W:          [5, 16]      float32
//   out:        [32000*200, 16] float32
//
// Decomposition: out[row, f] = relu( d0*W[0,f] + d1*W[1,f] + d2*W[2,f]
//                                    + d4*W[4,f] + eid*W[3,f] )
// The first 4 terms depend only on (cluster, pos) -> precompute into g_base
// (12.8 MB, L2-resident on re-read; each base row reused ~32x).
// Output stores use __stcs (evict-first) so the 410 MB write stream does not
// evict g_base from L2.

#define VPC   100          // CLUST_SIZE
#define NF    16           // N_FEAT
#define MAX_BASE_ENTRIES (2000 * 100)   // N_CLUST * CLUST_SIZE

// 12.8 MB scratch: per-(cluster,pos) partial feature rows, stored as float4[4].
__device__ float4 g_base[MAX_BASE_ENTRIES * (NF / 4)];

// ---------------------------------------------------------------------------
// Kernel 1: precompute base[c*V+p][0..15] = d0*W0 + d1*W1 + d2*W2 + d4*W4
// One thread per (cluster, pos) entry. W is tiny (80 floats) -> L1 broadcast.
// g_base stores keep default cache policy (we WANT them L2-resident).
// ---------------------------------------------------------------------------
__global__ void precompute_base_kernel(const float* __restrict__ data,
                                       const int*   __restrict__ clusts,
                                       const float* __restrict__ W,
                                       int total)
{
    int idx = blockIdx.x * blockDim.x + threadIdx.x;
    if (idx >= total) return;

    int v = clusts[idx];
    const float* dp = data + (long long)v * 5;
    float d0 = dp[0];
    float d1 = dp[1];
    float d2 = dp[2];
    float d4 = dp[4];   // column 3 is replaced by edge id later

    float4* out = g_base + idx * (NF / 4);
#pragma unroll
    for (int q = 0; q < NF / 4; q++) {
        float4 r;
        float* rp = reinterpret_cast<float*>(&r);
#pragma unroll
        for (int j = 0; j < 4; j++) {
            int f = q * 4 + j;
            rp[j] = d0 * __ldg(&W[0 * NF + f])
                  + d1 * __ldg(&W[1 * NF + f])
                  + d2 * __ldg(&W[2 * NF + f])
                  + d4 * __ldg(&W[4 * NF + f]);
        }
        out[q] = r;
    }
}

// ---------------------------------------------------------------------------
// Kernel 2: EPB edges per block, 256 threads. Per edge: 2V rows * NF floats
// = 800 float4. f4 = tid & 3 is loop-invariant (stride 256 divisible by 4),
// so the per-thread eid*W3 offset vector is computed once per edge.
// Reads of g_base are L2-resident; output stores are streaming (__stcs) and
// fully coalesced.
// ---------------------------------------------------------------------------
#define EPB 8   // edges per block

__global__ __launch_bounds__(256)
void edge_feature_kernel(const int*   __restrict__ edge_index,
                         const float* __restrict__ W,
                         float4*      __restrict__ out,
                         int E)
{
    const int t  = threadIdx.x;
    const int f4 = t & 3;

    // Per-thread W[3] slice (loop-invariant across edges).
    const float* W3 = W + 3 * NF + f4 * 4;
    const float w3x = __ldg(&W3[0]);
    const float w3y = __ldg(&W3[1]);
    const float w3z = __ldg(&W3[2]);
    const float w3w = __ldg(&W3[3]);

    const int F4_PER_EDGE = 2 * VPC * (NF / 4);  // 800

#pragma unroll
    for (int ee = 0; ee < EPB; ee++) {
        const int e = blockIdx.x * EPB + ee;
        if (e >= E) return;

        const int c0 = __ldg(&edge_index[e]);        // src cluster
        const int c1 = __ldg(&edge_index[E + e]);    // dst cluster
        const float eidf = (float)e;

        float4 off;
        off.x = eidf * w3x;
        off.y = eidf * w3y;
        off.z = eidf * w3z;
        off.w = eidf * w3w;

        float4* dst = out + (long long)e * F4_PER_EDGE;

#pragma unroll
        for (int k = 0; k < 4; k++) {
            int i = t + k * 256;
            if (i < F4_PER_EDGE) {
                int row = i >> 2;                       // 0..199
                int c   = (row < VPC) ? c0 : c1;
                int p   = (row < VPC) ? row : row - VPC;
                float4 b = g_base[(c * VPC + p) * (NF / 4) + f4];
                float4 r;
                r.x = fmaxf(b.x + off.x, 0.0f);
                r.y = fmaxf(b.y + off.y, 0.0f);
                r.z = fmaxf(b.z + off.z, 0.0f);
                r.w = fmaxf(b.w + off.w, 0.0f);
                __stcs(&dst[i], r);   // streaming store: don't pollute L2
            }
        }
    }
}

// ---------------------------------------------------------------------------
// kernel_launch: graph-capturable, allocation-free.
// Input order (metadata): data, clusts, edge_index, W.
// ---------------------------------------------------------------------------
extern "C" void kernel_launch(void* const* d_in, const int* in_sizes, int n_in,
                              void* d_out, int out_size)
{
    const float* data       = (const float*)d_in[0];
    const int*   clusts     = (const int*)  d_in[1];
    const int*   edge_index = (const int*)  d_in[2];
    const float* W          = (const float*)d_in[3];

    const int total_entries = in_sizes[1];      // N_CLUST * CLUST_SIZE = 200000
    const int E             = in_sizes[2] / 2;  // 32000

    // Kernel 1: fill g_base
    {
        int threads = 256;
        int blocks = (total_entries + threads - 1) / threads;
        precompute_base_kernel<<<blocks, threads>>>(data, clusts, W, total_entries);
    }

    // Kernel 2: EPB edges per block
    {
        int blocks = (E + EPB - 1) / EPB;
        edge_feature_kernel<<<blocks, 256>>>(edge_index, W, (float4*)d_out, E);
    }
}

// round 5
// speedup vs baseline: 1.1667x; 1.0838x over previous
#include <cuda_runtime.h>
#include <cuda_bf16.h>

// Problem constants (fixed for this bench):
//   data:       [200000, 5]  float32
//   clusts:     [2000, 100]  int32   (200000 entries total)
//   edge_index: [2, 32000]   int32
//   W:          [5, 16]      float32
//   out:        [32000*200, 16] float32
//
// out[row, f] = relu( d0*W[0,f] + d1*W[1,f] + d2*W[2,f] + d4*W[4,f] + eid*W[3,f] )
//
// R4 finding: with a 64 B/row precomputed feature base, L2 moves 820 MB and
// hits the LTS chip cap (~6300 B/cyc) at exactly the measured 73 us.
// Fix: precompute only the packed 16 B gather (d0,d1,d2,d4) per (cluster,pos)
// (3.2 MB, L2-resident) and reconstruct the 16 features with register FMAs.
// L2 traffic drops to ~515 MB; the kernel becomes DRAM-write-bound.

#define VPC   100          // CLUST_SIZE
#define NF    16           // N_FEAT
#define MAX_BASE_ENTRIES (2000 * 100)   // N_CLUST * CLUST_SIZE

// 3.2 MB scratch: packed (d0,d1,d2,d4) per (cluster,pos), 16-B aligned.
__device__ float4 g_pack[MAX_BASE_ENTRIES];

// ---------------------------------------------------------------------------
// Kernel 1: gather g_pack[idx] = (d0,d1,d2,d4) of voxel clusts[idx].
// ---------------------------------------------------------------------------
__global__ void gather_pack_kernel(const float* __restrict__ data,
                                   const int*   __restrict__ clusts,
                                   int total)
{
    int idx = blockIdx.x * blockDim.x + threadIdx.x;
    if (idx >= total) return;

    int v = clusts[idx];
    const float* dp = data + (long long)v * 5;
    float4 r;
    r.x = __ldg(&dp[0]);
    r.y = __ldg(&dp[1]);
    r.z = __ldg(&dp[2]);
    r.w = __ldg(&dp[4]);   // column 3 is replaced by edge id later
    g_pack[idx] = r;
}

// ---------------------------------------------------------------------------
// Kernel 2: EPB edges per block, 256 threads. Per edge: 200 rows * 16 floats
// = 800 float4 stores. Lane group of 4 (f4 = t&3) shares one packed 16-B read
// (single sector, broadcast) and each lane produces 4 features via FMA.
// Weights are hoisted into registers (loop-invariant per lane).
// ---------------------------------------------------------------------------
#define EPB 8   // edges per block

__global__ __launch_bounds__(256)
void edge_feature_kernel(const int*   __restrict__ edge_index,
                         const float* __restrict__ W,
                         float4*      __restrict__ out,
                         int E)
{
    const int t  = threadIdx.x;
    const int f4 = t & 3;
    const int fb = f4 * 4;   // first feature this lane produces

    // Hoist this lane's 20 weights: W[k][fb+j], k in {0,1,2,4} plus W[3].
    float w0[4], w1[4], w2[4], w3[4], w4[4];
#pragma unroll
    for (int j = 0; j < 4; j++) {
        w0[j] = __ldg(&W[0 * NF + fb + j]);
        w1[j] = __ldg(&W[1 * NF + fb + j]);
        w2[j] = __ldg(&W[2 * NF + fb + j]);
        w3[j] = __ldg(&W[3 * NF + fb + j]);
        w4[j] = __ldg(&W[4 * NF + fb + j]);
    }

    const int F4_PER_EDGE = 2 * VPC * (NF / 4);  // 800

#pragma unroll
    for (int ee = 0; ee < EPB; ee++) {
        const int e = blockIdx.x * EPB + ee;
        if (e >= E) return;

        const int c0 = __ldg(&edge_index[e]);        // src cluster
        const int c1 = __ldg(&edge_index[E + e]);    // dst cluster
        const float eidf = (float)e;

        // Per-lane eid * W[3] offsets for this edge.
        float off[4];
#pragma unroll
        for (int j = 0; j < 4; j++) off[j] = eidf * w3[j];

        float4* dst = out + (long long)e * F4_PER_EDGE;

#pragma unroll
        for (int k = 0; k < 4; k++) {
            int i = t + k * 256;
            if (i < F4_PER_EDGE) {
                int row = i >> 2;                       // 0..199
                int c   = (row < VPC) ? c0 : c1;
                int p   = (row < VPC) ? row : row - VPC;
                float4 d = g_pack[c * VPC + p];         // 16 B, broadcast x4 lanes

                float4 r;
                r.x = fmaxf(fmaf(d.x, w0[0], fmaf(d.y, w1[0],
                            fmaf(d.z, w2[0], fmaf(d.w, w4[0], off[0])))), 0.0f);
                r.y = fmaxf(fmaf(d.x, w0[1], fmaf(d.y, w1[1],
                            fmaf(d.z, w2[1], fmaf(d.w, w4[1], off[1])))), 0.0f);
                r.z = fmaxf(fmaf(d.x, w0[2], fmaf(d.y, w1[2],
                            fmaf(d.z, w2[2], fmaf(d.w, w4[2], off[2])))), 0.0f);
                r.w = fmaxf(fmaf(d.x, w0[3], fmaf(d.y, w1[3],
                            fmaf(d.z, w2[3], fmaf(d.w, w4[3], off[3])))), 0.0f);

                __stcs(&dst[i], r);   // streaming store: output never re-read
            }
        }
    }
}

// ---------------------------------------------------------------------------
// kernel_launch: graph-capturable, allocation-free.
// Input order (metadata): data, clusts, edge_index, W.
// ---------------------------------------------------------------------------
extern "C" void kernel_launch(void* const* d_in, const int* in_sizes, int n_in,
                              void* d_out, int out_size)
{
    const float* data       = (const float*)d_in[0];
    const int*   clusts     = (const int*)  d_in[1];
    const int*   edge_index = (const int*)  d_in[2];
    const float* W          = (const float*)d_in[3];

    const int total_entries = in_sizes[1];      // N_CLUST * CLUST_SIZE = 200000
    const int E             = in_sizes[2] / 2;  // 32000

    // Kernel 1: packed gather (3.2 MB, stays in L2)
    {
        int threads = 256;
        int blocks = (total_entries + threads - 1) / threads;
        gather_pack_kernel<<<blocks, threads>>>(data, clusts, total_entries);
    }

    // Kernel 2: EPB edges per block
    {
        int blocks = (E + EPB - 1) / EPB;
        edge_feature_kernel<<<blocks, 256>>>(edge_index, W, (float4*)d_out, E);
    }
}

// round 8
// speedup vs baseline: 1.2347x; 1.0583x over previous
#include <cuda_runtime.h>
#include <cuda_bf16.h>

// Problem constants (fixed for this bench):
//   data:       [200000, 5]  float32
//   clusts:     [2000, 100]  int32   (200000 entries total)
//   edge_index: [2, 32000]   int32
//   W:          [5, 16]      float32
//   out:        [32000*200, 16] float32
//
// out[row, f] = relu( d0*W[0,f] + d1*W[1,f] + d2*W[2,f] + d4*W[4,f] + eid*W[3,f] )
//
// R5 finding: FMA-reconstruct cut L2 traffic but lost occupancy (40 regs ->
// 65.6%), starving the DRAM write stream. This round: launch_bounds(256,6)
// (42-reg budget -> no spills, occ 75%) plus a predicate-free mapping
// (block = 8 edges = 6400 float4 = 25 exact iterations of 256 threads;
// 800 % 32 == 0 so the edge-local index is warp-uniform).

#define VPC   100          // CLUST_SIZE
#define NF    16           // N_FEAT
#define MAX_BASE_ENTRIES (2000 * 100)   // N_CLUST * CLUST_SIZE
#define F4E   (2 * VPC * (NF / 4))      // 800 float4 per edge
#define EPB   8                          // edges per block
#define ITERS (EPB * F4E / 256)          // 25

// 3.2 MB scratch: packed (d0,d1,d2,d4) per (cluster,pos), 16-B aligned.
__device__ float4 g_pack[MAX_BASE_ENTRIES];

// ---------------------------------------------------------------------------
// Kernel 1: gather g_pack[idx] = (d0,d1,d2,d4) of voxel clusts[idx].
// ---------------------------------------------------------------------------
__global__ void gather_pack_kernel(const float* __restrict__ data,
                                   const int*   __restrict__ clusts,
                                   int total)
{
    int idx = blockIdx.x * blockDim.x + threadIdx.x;
    if (idx >= total) return;

    int v = clusts[idx];
    const float* dp = data + (long long)v * 5;
    float4 r;
    r.x = __ldg(&dp[0]);
    r.y = __ldg(&dp[1]);
    r.z = __ldg(&dp[2]);
    r.w = __ldg(&dp[4]);   // column 3 is replaced by edge id later
    g_pack[idx] = r;
}

// ---------------------------------------------------------------------------
// Kernel 2: block = EPB edges, 256 threads, ITERS exact full iterations.
// Lane group of 4 (f4 = t&3) shares one packed 16-B read (broadcast);
// each lane produces 4 features with a 5-term FMA chain (eid term folded in).
// Stores are streaming (__stcs) and fully coalesced.
// ---------------------------------------------------------------------------
__global__ __launch_bounds__(256, 6)
void edge_feature_kernel(const int*   __restrict__ edge_index,
                         const float* __restrict__ W,
                         float4*      __restrict__ out,
                         int E)
{
    __shared__ int s_c0[EPB];
    __shared__ int s_c1[EPB];

    const int t      = threadIdx.x;
    const int e_base = blockIdx.x * EPB;

    if (t < EPB) {
        int e = e_base + t;
        if (e < E) {
            s_c0[t] = edge_index[e];
            s_c1[t] = edge_index[E + e];
        } else {
            s_c0[t] = 0;
            s_c1[t] = 0;
        }
    }

    // Hoist this lane's 20 weights: W[k][fb..fb+3], k in 0..4.
    const int f4 = t & 3;
    const int fb = f4 * 4;
    float w0[4], w1[4], w2[4], w3[4], w4[4];
#pragma unroll
    for (int j = 0; j < 4; j++) {
        w0[j] = __ldg(&W[0 * NF + fb + j]);
        w1[j] = __ldg(&W[1 * NF + fb + j]);
        w2[j] = __ldg(&W[2 * NF + fb + j]);
        w3[j] = __ldg(&W[3 * NF + fb + j]);
        w4[j] = __ldg(&W[4 * NF + fb + j]);
    }
    __syncthreads();

    // Number of valid float4 slots for this block (full blocks: EPB*F4E).
    const int lim = min(EPB, E - e_base) * F4E;
    float4* dstB = out + (long long)e_base * F4E;

#pragma unroll 5
    for (int k = 0; k < ITERS; k++) {
        int i = t + k * 256;
        if (i < lim) {
            int el  = i / F4E;            // warp-uniform (800 % 32 == 0)
            int rem = i - el * F4E;
            int row = rem >> 2;           // 0..199
            int c   = (row < VPC) ? s_c0[el] : s_c1[el];
            int p   = (row < VPC) ? row : row - VPC;
            float4 d = g_pack[c * VPC + p];        // 16 B, broadcast x4 lanes

            float eidf = (float)(e_base + el);
            float4 r;
            r.x = fmaxf(fmaf(d.x, w0[0], fmaf(d.y, w1[0], fmaf(d.z, w2[0],
                        fmaf(d.w, w4[0], eidf * w3[0])))), 0.0f);
            r.y = fmaxf(fmaf(d.x, w0[1], fmaf(d.y, w1[1], fmaf(d.z, w2[1],
                        fmaf(d.w, w4[1], eidf * w3[1])))), 0.0f);
            r.z = fmaxf(fmaf(d.x, w0[2], fmaf(d.y, w1[2], fmaf(d.z, w2[2],
                        fmaf(d.w, w4[2], eidf * w3[2])))), 0.0f);
            r.w = fmaxf(fmaf(d.x, w0[3], fmaf(d.y, w1[3], fmaf(d.z, w2[3],
                        fmaf(d.w, w4[3], eidf * w3[3])))), 0.0f);

            __stcs(&dstB[i], r);   // streaming store: output never re-read
        }
    }
}

// ---------------------------------------------------------------------------
// kernel_launch: graph-capturable, allocation-free.
// Input order (metadata): data, clusts, edge_index, W.
// ---------------------------------------------------------------------------
extern "C" void kernel_launch(void* const* d_in, const int* in_sizes, int n_in,
                              void* d_out, int out_size)
{
    const float* data       = (const float*)d_in[0];
    const int*   clusts     = (const int*)  d_in[1];
    const int*   edge_index = (const int*)  d_in[2];
    const float* W          = (const float*)d_in[3];

    const int total_entries = in_sizes[1];      // N_CLUST * CLUST_SIZE = 200000
    const int E             = in_sizes[2] / 2;  // 32000

    // Kernel 1: packed gather (3.2 MB, stays in L2)
    {
        int threads = 256;
        int blocks = (total_entries + threads - 1) / threads;
        gather_pack_kernel<<<blocks, threads>>>(data, clusts, total_entries);
    }

    // Kernel 2: EPB edges per block, predicate-free full iterations
    {
        int blocks = (E + EPB - 1) / EPB;
        edge_feature_kernel<<<blocks, 256>>>(edge_index, W, (float4*)d_out, E);
    }
}

// round 9
// speedup vs baseline: 1.2353x; 1.0005x over previous
#include <cuda_runtime.h>
#include <cuda_bf16.h>

// Problem constants (fixed for this bench):
//   data:       [200000, 5]  float32
//   clusts:     [2000, 100]  int32   (200000 entries total)
//   edge_index: [2, 32000]   int32
//   W:          [5, 16]      float32
//   out:        [32000*200, 16] float32
//
// out[row, f] = relu( d0*W[0,f] + d1*W[1,f] + d2*W[2,f] + d4*W[4,f] + eid*W[3,f] )
//
// R5 finding: FMA-reconstruct cut L2 traffic but lost occupancy (40 regs ->
// 65.6%), starving the DRAM write stream. This round: launch_bounds(256,6)
// (42-reg budget -> no spills, occ 75%) plus a predicate-free mapping
// (block = 8 edges = 6400 float4 = 25 exact iterations of 256 threads;
// 800 % 32 == 0 so the edge-local index is warp-uniform).

#define VPC   100          // CLUST_SIZE
#define NF    16           // N_FEAT
#define MAX_BASE_ENTRIES (2000 * 100)   // N_CLUST * CLUST_SIZE
#define F4E   (2 * VPC * (NF / 4))      // 800 float4 per edge
#define EPB   8                          // edges per block
#define ITERS (EPB * F4E / 256)          // 25

// 3.2 MB scratch: packed (d0,d1,d2,d4) per (cluster,pos), 16-B aligned.
__device__ float4 g_pack[MAX_BASE_ENTRIES];

// ---------------------------------------------------------------------------
// Kernel 1: gather g_pack[idx] = (d0,d1,d2,d4) of voxel clusts[idx].
// ---------------------------------------------------------------------------
__global__ void gather_pack_kernel(const float* __restrict__ data,
                                   const int*   __restrict__ clusts,
                                   int total)
{
    int idx = blockIdx.x * blockDim.x + threadIdx.x;
    if (idx >= total) return;

    int v = clusts[idx];
    const float* dp = data + (long long)v * 5;
    float4 r;
    r.x = __ldg(&dp[0]);
    r.y = __ldg(&dp[1]);
    r.z = __ldg(&dp[2]);
    r.w = __ldg(&dp[4]);   // column 3 is replaced by edge id later
    g_pack[idx] = r;
}

// ---------------------------------------------------------------------------
// Kernel 2: block = EPB edges, 256 threads, ITERS exact full iterations.
// Lane group of 4 (f4 = t&3) shares one packed 16-B read (broadcast);
// each lane produces 4 features with a 5-term FMA chain (eid term folded in).
// Stores are streaming (__stcs) and fully coalesced.
// ---------------------------------------------------------------------------
__global__ __launch_bounds__(256, 6)
void edge_feature_kernel(const int*   __restrict__ edge_index,
                         const float* __restrict__ W,
                         float4*      __restrict__ out,
                         int E)
{
    __shared__ int s_c0[EPB];
    __shared__ int s_c1[EPB];

    const int t      = threadIdx.x;
    const int e_base = blockIdx.x * EPB;

    if (t < EPB) {
        int e = e_base + t;
        if (e < E) {
            s_c0[t] = edge_index[e];
            s_c1[t] = edge_index[E + e];
        } else {
            s_c0[t] = 0;
            s_c1[t] = 0;
        }
    }

    // Hoist this lane's 20 weights: W[k][fb..fb+3], k in 0..4.
    const int f4 = t & 3;
    const int fb = f4 * 4;
    float w0[4], w1[4], w2[4], w3[4], w4[4];
#pragma unroll
    for (int j = 0; j < 4; j++) {
        w0[j] = __ldg(&W[0 * NF + fb + j]);
        w1[j] = __ldg(&W[1 * NF + fb + j]);
        w2[j] = __ldg(&W[2 * NF + fb + j]);
        w3[j] = __ldg(&W[3 * NF + fb + j]);
        w4[j] = __ldg(&W[4 * NF + fb + j]);
    }
    __syncthreads();

    // Number of valid float4 slots for this block (full blocks: EPB*F4E).
    const int lim = min(EPB, E - e_base) * F4E;
    float4* dstB = out + (long long)e_base * F4E;

#pragma unroll 5
    for (int k = 0; k < ITERS; k++) {
        int i = t + k * 256;
        if (i < lim) {
            int el  = i / F4E;            // warp-uniform (800 % 32 == 0)
            int rem = i - el * F4E;
            int row = rem >> 2;           // 0..199
            int c   = (row < VPC) ? s_c0[el] : s_c1[el];
            int p   = (row < VPC) ? row : row - VPC;
            float4 d = g_pack[c * VPC + p];        // 16 B, broadcast x4 lanes

            float eidf = (float)(e_base + el);
            float4 r;
            r.x = fmaxf(fmaf(d.x, w0[0], fmaf(d.y, w1[0], fmaf(d.z, w2[0],
                        fmaf(d.w, w4[0], eidf * w3[0])))), 0.0f);
            r.y = fmaxf(fmaf(d.x, w0[1], fmaf(d.y, w1[1], fmaf(d.z, w2[1],
                        fmaf(d.w, w4[1], eidf * w3[1])))), 0.0f);
            r.z = fmaxf(fmaf(d.x, w0[2], fmaf(d.y, w1[2], fmaf(d.z, w2[2],
                        fmaf(d.w, w4[2], eidf * w3[2])))), 0.0f);
            r.w = fmaxf(fmaf(d.x, w0[3], fmaf(d.y, w1[3], fmaf(d.z, w2[3],
                        fmaf(d.w, w4[3], eidf * w3[3])))), 0.0f);

            __stcs(&dstB[i], r);   // streaming store: output never re-read
        }
    }
}

// ---------------------------------------------------------------------------
// kernel_launch: graph-capturable, allocation-free.
// Input order (metadata): data, clusts, edge_index, W.
// ---------------------------------------------------------------------------
extern "C" void kernel_launch(void* const* d_in, const int* in_sizes, int n_in,
                              void* d_out, int out_size)
{
    const float* data       = (const float*)d_in[0];
    const int*   clusts     = (const int*)  d_in[1];
    const int*   edge_index = (const int*)  d_in[2];
    const float* W          = (const float*)d_in[3];

    const int total_entries = in_sizes[1];      // N_CLUST * CLUST_SIZE = 200000
    const int E             = in_sizes[2] / 2;  // 32000

    // Kernel 1: packed gather (3.2 MB, stays in L2)
    {
        int threads = 256;
        int blocks = (total_entries + threads - 1) / threads;
        gather_pack_kernel<<<blocks, threads>>>(data, clusts, total_entries);
    }

    // Kernel 2: EPB edges per block, predicate-free full iterations
    {
        int blocks = (E + EPB - 1) / EPB;
        edge_feature_kernel<<<blocks, 256>>>(edge_index, W, (float4*)d_out, E);
    }
}